// round 10
// baseline (speedup 1.0000x reference)
#include <cuda_runtime.h>
#include <math.h>

constexpr int NB = 128, NA = 2, NH = 128, NW = 128;
constexpr int PLANE = NH * NW;
constexpr float THRESH = 0.6f;
constexpr float OBJ_SCALE = 5.0f;
constexpr float LN_MARGIN = 0.55961579f;   // ln(1.75) > ln(5/3)+fastlog-err margin
constexpr float POS_MARGIN = 1.30f;        // > 1.2889 exact positional bound
constexpr int NBLOCKS = 2048;              // 524288 threads * 8 cells

// Accumulators (zero at module load; reset by last block each run)
__device__ double g_conf2 = 0.0;
__device__ unsigned long long g_cnt = 0ull;
__device__ float  g_sel = 0.0f;
__device__ unsigned g_done = 0u;

__device__ __forceinline__ float sig_fast(float x) {
    return __fdividef(1.0f, 1.0f + __expf(-x));
}

// 256-bit L2-pinned load (sm_103a requires v8.b32 for L2::evict_last).
// Tensor (~54MB touched) fits in ~126MB L2; replays re-read it identically.
__device__ __forceinline__ void ldg_evl8(const float* p, float* v) {
    unsigned r0, r1, r2, r3, r4, r5, r6, r7;
    asm("ld.global.nc.L2::evict_last.v8.b32 {%0,%1,%2,%3,%4,%5,%6,%7}, [%8];"
        : "=r"(r0), "=r"(r1), "=r"(r2), "=r"(r3),
          "=r"(r4), "=r"(r5), "=r"(r6), "=r"(r7)
        : "l"(p));
    v[0] = __uint_as_float(r0); v[1] = __uint_as_float(r1);
    v[2] = __uint_as_float(r2); v[3] = __uint_as_float(r3);
    v[4] = __uint_as_float(r4); v[5] = __uint_as_float(r5);
    v[6] = __uint_as_float(r6); v[7] = __uint_as_float(r7);
}

__global__ void __launch_bounds__(256) k_fused(const float* __restrict__ out,
                                               const float* __restrict__ tgt,
                                               const float* __restrict__ anc,
                                               float* __restrict__ res) {
    int tid = blockIdx.x * 256 + threadIdx.x;
    int i8 = (tid & 15) * 8;          // 8 contiguous columns
    int r  = tid >> 4;
    int j  = r & 127; r >>= 7;        // row
    int a  = r & 1;                   // anchor (block-uniform)
    int b  = r >> 1;                  // batch  (block-uniform)

    // ---- 3 front-batched 256-bit streaming loads: w, h, conf ----
    const float* pbase = out + ((size_t)(b * 10 + a * 5) * NH + j) * NW + i8;
    float pw8[8], ph8[8], pc8[8];
    ldg_evl8(pbase + 2 * (size_t)PLANE, pw8);
    ldg_evl8(pbase + 3 * (size_t)PLANE, ph8);
    ldg_evl8(pbase + 4 * (size_t)PLANE, pc8);

    // ---- per-thread constants (overlap in-flight loads) ----
    float4 t = __ldg((const float4*)(tgt + b * 4));     // warp-broadcast
    float gx = t.x * (float)NW, gy = t.y * (float)NH;
    float gw = t.z * (float)NW, gh = t.w * (float)NH;
    float a0w = __ldg(anc + 0), a0h = __ldg(anc + 1);
    float a1w = __ldg(anc + 2), a1h = __ldg(anc + 3);

    float ga = gw * gh;
    float i0v = fminf(gw, a0w) * fminf(gh, a0h);
    float u0v = ga + 1e-16f + a0w * a0h - i0v;
    float i1v = fminf(gw, a1w) * fminf(gh, a1h);
    float u1v = ga + 1e-16f + a1w * a1h - i1v;
    int best = (i1v * u0v > i0v * u1v) ? 1 : 0;         // u0,u1 > 0

    int excl = best * PLANE + (int)gy * NW + (int)gx;
    int kx = excl - (a * PLANE + j * NW + i8);           // [0,8) iff owned

    float aw = a ? a1w : a0w;
    float ah = a ? a1h : a0h;
    float cc = __logf(__fdividef(ga, aw * ah));
    float lo = cc - LN_MARGIN, hi = cc + LN_MARGIN;

    // position screen: iou>0.6 impossible outside gx±1.3gw / gy±1.3gh
    float colLo = gx - POS_MARGIN * gw - 1.0f;
    float colHi = gx + POS_MARGIN * gw;
    float fj = (float)j;
    bool rowok = (fj > gy - POS_MARGIN * gh - 1.0f) && (fj < gy + POS_MARGIN * gh);

    bool pass[8];
    bool anyp = false;
    #pragma unroll
    for (int k = 0; k < 8; k++) {
        float s  = pw8[k] + ph8[k];
        float fi = (float)(i8 + k);
        pass[k] = (s > lo) && (s < hi) && rowok && (fi > colLo) && (fi < colHi);
        anyp |= pass[k];
    }
    bool own = (kx >= 0) && (kx < 8);
    bool noobj[8] = {true, true, true, true, true, true, true, true};
    float selv = 0.0f;

    if (anyp | own) {
        float px8[8], py8[8];
        ldg_evl8(pbase, px8);
        ldg_evl8(pbase + (size_t)PLANE, py8);
        float gxm = gx - gw * 0.5f, gxM = gx + gw * 0.5f;
        float gym = gy - gh * 0.5f, gyM = gy + gh * 0.5f;

        #pragma unroll
        for (int k = 0; k < 8; k++) {            // compile-time indices only
            bool is_excl = (k == kx);
            if (pass[k] | is_excl) {
                float px = sig_fast(px8[k]) + (float)(i8 + k);
                float py = sig_fast(py8[k]) + fj;
                float pw = __expf(pw8[k]) * aw;
                float ph = __expf(ph8[k]) * ah;
                float mx = fminf(px - pw * 0.5f, gxm);
                float Mx = fmaxf(px + pw * 0.5f, gxM);
                float my = fminf(py - ph * 0.5f, gym);
                float My = fmaxf(py + ph * 0.5f, gyM);
                float cw = pw + gw - (Mx - mx);
                float ch = ph + gh - (My - my);
                float carea = cw * ch;
                float uarea = pw * ph + ga - carea;
                noobj[k] = (cw <= 0.0f) || (ch <= 0.0f) || (carea <= THRESH * uarea);
                if (is_excl) {
                    noobj[k] = false;
                    // rare: sel-loss constants recomputed locally
                    float bw = best ? a1w : a0w;
                    float bh = best ? a1h : a0h;
                    float tscale = 2.0f - t.z * t.w;
                    float xs = sig_fast(px8[k]);
                    float ys = sig_fast(py8[k]);
                    float cs = sig_fast(pc8[k]);
                    float txv = gx - floorf(gx), tyv = gy - floorf(gy);
                    float twv = __logf(__fdividef(gw, bw) + 1e-16f);
                    float thv = __logf(__fdividef(gh, bh) + 1e-16f);
                    float dx = (xs - txv) * tscale, dy = (ys - tyv) * tscale;
                    float dw = (pw8[k] - twv) * tscale, dh = (ph8[k] - thv) * tscale;
                    selv += (dx*dx + dy*dy + dw*dw + dh*dh
                          + OBJ_SCALE * (cs - 1.0f) * (cs - 1.0f)) * (1.0f / (float)NB);
                }
            }
        }
    }

    float conf2f = 0.0f;
    int cnt = 0;
    #pragma unroll
    for (int k = 0; k < 8; k++) {
        if (noobj[k]) {
            float rr = sig_fast(pc8[k]);
            conf2f += rr * rr;
            cnt++;
        }
    }

    // ---- block reduce (conf2, cnt, selv) ----
    #pragma unroll
    for (int o = 16; o > 0; o >>= 1) {
        conf2f += __shfl_down_sync(0xffffffffu, conf2f, o);
        cnt    += __shfl_down_sync(0xffffffffu, cnt, o);
        selv   += __shfl_down_sync(0xffffffffu, selv, o);
    }
    __shared__ double sh_c2[8];
    __shared__ int    sh_ct[8];
    __shared__ float  sh_sv[8];
    int lane = threadIdx.x & 31, wrp = threadIdx.x >> 5;
    if (lane == 0) { sh_c2[wrp] = (double)conf2f; sh_ct[wrp] = cnt; sh_sv[wrp] = selv; }
    __syncthreads();
    if (wrp == 0) {
        double c2 = (lane < 8) ? sh_c2[lane] : 0.0;
        int    ct = (lane < 8) ? sh_ct[lane] : 0;
        float  sv = (lane < 8) ? sh_sv[lane] : 0.0f;
        #pragma unroll
        for (int o = 4; o > 0; o >>= 1) {
            c2 += __shfl_down_sync(0xffffffffu, c2, o);
            ct += __shfl_down_sync(0xffffffffu, ct, o);
            sv += __shfl_down_sync(0xffffffffu, sv, o);
        }
        if (lane == 0) {
            atomicAdd(&g_conf2, c2);
            atomicAdd(&g_cnt, (unsigned long long)ct);
            if (sv != 0.0f) atomicAdd(&g_sel, sv);
            __threadfence();
            unsigned old = atomicAdd(&g_done, 1u);
            if (old == (unsigned)(NBLOCKS - 1)) {
                __threadfence();
                res[0] = g_sel + (float)(g_conf2 / (double)g_cnt);
                g_conf2 = 0.0; g_cnt = 0ull; g_sel = 0.0f; g_done = 0u;
            }
        }
    }
}

extern "C" void kernel_launch(void* const* d_in, const int* in_sizes, int n_in,
                              void* d_out, int out_size) {
    const float* out = (const float*)d_in[0];   // (128, 10, 128, 128)
    const float* tgt = (const float*)d_in[1];   // (128, 4)
    const float* anc = (const float*)d_in[2];   // (2, 2)
    float* res = (float*)d_out;

    k_fused<<<NBLOCKS, 256>>>(out, tgt, anc, res);
}

// round 11
// speedup vs baseline: 1.1008x; 1.1008x over previous
#include <cuda_runtime.h>
#include <math.h>
#include <float.h>

constexpr int NB = 128, NA = 2, NH = 128, NW = 128;
constexpr int PLANE = NH * NW;
constexpr float THRESH = 0.6f;
constexpr float OBJ_SCALE = 5.0f;
constexpr float LN_MARGIN = 0.55961579f;   // ln(1.75) > ln(5/3)+fastlog-err margin
constexpr float POS_MARGIN = 1.30f;        // > 1.2889 exact positional bound
constexpr int NBLOCKS = 2048;              // 524288 threads * 8 cells
constexpr long long TOTAL_CELLS = (long long)NB * NA * NH * NW;  // 4194304

// Accumulators (zero at module load; reset by last block each run)
__device__ double g_conf2 = 0.0;
__device__ unsigned long long g_cnt = 0ull;   // corrections only (negative)
__device__ float  g_sel = 0.0f;
__device__ unsigned g_done = 0u;

__device__ __forceinline__ float sig_fast(float x) {
    return __fdividef(1.0f, 1.0f + __expf(-x));
}

__global__ void __launch_bounds__(256) k_fused(const float* __restrict__ out,
                                               const float* __restrict__ tgt,
                                               const float* __restrict__ anc,
                                               float* __restrict__ res) {
    int tid = blockIdx.x * 256 + threadIdx.x;
    int i8 = (tid & 15) * 8;          // 8 contiguous columns
    int r  = tid >> 4;
    int j  = r & 127; r >>= 7;        // row
    int a  = r & 1;                   // anchor (block-uniform)
    int b  = r >> 1;                  // batch  (block-uniform)

    // ---- 6 front-batched float4 loads: w, h, conf (always needed) ----
    const float* pbase = out + ((size_t)(b * 10 + a * 5) * NH + j) * NW + i8;
    float4 w0 = *(const float4*)(pbase + 2 * (size_t)PLANE);
    float4 w1 = *(const float4*)(pbase + 2 * (size_t)PLANE + 4);
    float4 h0 = *(const float4*)(pbase + 3 * (size_t)PLANE);
    float4 h1 = *(const float4*)(pbase + 3 * (size_t)PLANE + 4);
    float4 c0 = *(const float4*)(pbase + 4 * (size_t)PLANE);
    float4 c1 = *(const float4*)(pbase + 4 * (size_t)PLANE + 4);

    // ---- per-thread constants (overlap in-flight loads) ----
    float4 t = __ldg((const float4*)(tgt + b * 4));     // warp-broadcast
    float gx = t.x * (float)NW, gy = t.y * (float)NH;
    float gw = t.z * (float)NW, gh = t.w * (float)NH;
    float a0w = __ldg(anc + 0), a0h = __ldg(anc + 1);
    float a1w = __ldg(anc + 2), a1h = __ldg(anc + 3);

    float ga = gw * gh;
    float i0v = fminf(gw, a0w) * fminf(gh, a0h);
    float u0v = ga + 1e-16f + a0w * a0h - i0v;
    float i1v = fminf(gw, a1w) * fminf(gh, a1h);
    float u1v = ga + 1e-16f + a1w * a1h - i1v;
    int best = (i1v * u0v > i0v * u1v) ? 1 : 0;         // u0,u1 > 0

    int excl = best * PLANE + (int)gy * NW + (int)gx;
    int kx = excl - (a * PLANE + j * NW + i8);           // [0,8) iff owned

    float aw = a ? a1w : a0w;
    float ah = a ? a1h : a0h;
    float cc = __logf(__fdividef(ga, aw * ah));
    float lo = cc - LN_MARGIN, hi = cc + LN_MARGIN;

    // position screen folded to THREAD granularity: if this thread's 8-col
    // range can't intersect gx±1.3gw (or row outside gy±1.3gh), no cell in
    // it can have iou>0.6 -> disable the area screen entirely (lo=+INF).
    float fj = (float)j;
    bool rowok = (fj > gy - POS_MARGIN * gh - 1.0f) && (fj < gy + POS_MARGIN * gh);
    bool colok = ((float)(i8 + 7) > gx - POS_MARGIN * gw - 1.0f) &&
                 ((float)i8      < gx + POS_MARGIN * gw);
    if (!(rowok && colok)) { lo = FLT_MAX; hi = -FLT_MAX; }

    float pw8[8] = {w0.x,w0.y,w0.z,w0.w,w1.x,w1.y,w1.z,w1.w};
    float ph8[8] = {h0.x,h0.y,h0.z,h0.w,h1.x,h1.y,h1.z,h1.w};
    float pc8[8] = {c0.x,c0.y,c0.z,c0.w,c1.x,c1.y,c1.z,c1.w};

    // ---- HOT LOOP: straight-line, no predication on the accumulate ----
    float conf2f = 0.0f;
    bool pass[8];
    bool anyp = false;
    #pragma unroll
    for (int k = 0; k < 8; k++) {
        float s = pw8[k] + ph8[k];
        pass[k] = (s > lo) && (s < hi);
        anyp |= pass[k];
        float rr = sig_fast(pc8[k]);
        conf2f += rr * rr;                 // unconditional; corrected below
    }

    // ---- rare slow path: corrections + selected-cell loss ----
    bool own = (kx >= 0) && (kx < 8);
    float selv = 0.0f;
    int cnt = 0;                           // correction count (negative)
    if (anyp | own) {
        float px8[8], py8[8];
        float4 x0 = *(const float4*)(pbase);
        float4 x1 = *(const float4*)(pbase + 4);
        float4 y0 = *(const float4*)(pbase + (size_t)PLANE);
        float4 y1 = *(const float4*)(pbase + (size_t)PLANE + 4);
        px8[0]=x0.x; px8[1]=x0.y; px8[2]=x0.z; px8[3]=x0.w;
        px8[4]=x1.x; px8[5]=x1.y; px8[6]=x1.z; px8[7]=x1.w;
        py8[0]=y0.x; py8[1]=y0.y; py8[2]=y0.z; py8[3]=y0.w;
        py8[4]=y1.x; py8[5]=y1.y; py8[6]=y1.z; py8[7]=y1.w;

        float gxm = gx - gw * 0.5f, gxM = gx + gw * 0.5f;
        float gym = gy - gh * 0.5f, gyM = gy + gh * 0.5f;

        #pragma unroll
        for (int k = 0; k < 8; k++) {      // compile-time indices only
            bool is_excl = (k == kx);
            if (pass[k] | is_excl) {
                float px = sig_fast(px8[k]) + (float)(i8 + k);
                float py = sig_fast(py8[k]) + fj;
                float pw = __expf(pw8[k]) * aw;
                float ph = __expf(ph8[k]) * ah;
                float mx = fminf(px - pw * 0.5f, gxm);
                float Mx = fmaxf(px + pw * 0.5f, gxM);
                float my = fminf(py - ph * 0.5f, gym);
                float My = fmaxf(py + ph * 0.5f, gyM);
                float cw = pw + gw - (Mx - mx);
                float ch = ph + gh - (My - my);
                float carea = cw * ch;
                float uarea = pw * ph + ga - carea;
                bool noobj = (cw <= 0.0f) || (ch <= 0.0f) || (carea <= THRESH * uarea);
                // cell must NOT be counted if (pass && !noobj) or excluded
                if ((pass[k] && !noobj) || is_excl) {
                    float rr = sig_fast(pc8[k]);   // identical recompute: exact cancel
                    conf2f -= rr * rr;
                    cnt--;
                }
                if (is_excl) {
                    float bw = best ? a1w : a0w;
                    float bh = best ? a1h : a0h;
                    float tscale = 2.0f - t.z * t.w;
                    float xs = sig_fast(px8[k]);
                    float ys = sig_fast(py8[k]);
                    float cs = sig_fast(pc8[k]);
                    float txv = gx - floorf(gx), tyv = gy - floorf(gy);
                    float twv = __logf(__fdividef(gw, bw) + 1e-16f);
                    float thv = __logf(__fdividef(gh, bh) + 1e-16f);
                    float dx = (xs - txv) * tscale, dy = (ys - tyv) * tscale;
                    float dw = (pw8[k] - twv) * tscale, dh = (ph8[k] - thv) * tscale;
                    selv += (dx*dx + dy*dy + dw*dw + dh*dh
                          + OBJ_SCALE * (cs - 1.0f) * (cs - 1.0f)) * (1.0f / (float)NB);
                }
            }
        }
    }

    // ---- block reduce (conf2, cnt, selv) ----
    #pragma unroll
    for (int o = 16; o > 0; o >>= 1) {
        conf2f += __shfl_down_sync(0xffffffffu, conf2f, o);
        cnt    += __shfl_down_sync(0xffffffffu, cnt, o);
        selv   += __shfl_down_sync(0xffffffffu, selv, o);
    }
    __shared__ double sh_c2[8];
    __shared__ int    sh_ct[8];
    __shared__ float  sh_sv[8];
    int lane = threadIdx.x & 31, wrp = threadIdx.x >> 5;
    if (lane == 0) { sh_c2[wrp] = (double)conf2f; sh_ct[wrp] = cnt; sh_sv[wrp] = selv; }
    __syncthreads();
    if (wrp == 0) {
        double c2 = (lane < 8) ? sh_c2[lane] : 0.0;
        int    ct = (lane < 8) ? sh_ct[lane] : 0;
        float  sv = (lane < 8) ? sh_sv[lane] : 0.0f;
        #pragma unroll
        for (int o = 4; o > 0; o >>= 1) {
            c2 += __shfl_down_sync(0xffffffffu, c2, o);
            ct += __shfl_down_sync(0xffffffffu, ct, o);
            sv += __shfl_down_sync(0xffffffffu, sv, o);
        }
        if (lane == 0) {
            atomicAdd(&g_conf2, c2);
            if (ct != 0) atomicAdd(&g_cnt, (unsigned long long)(long long)ct);
            if (sv != 0.0f) atomicAdd(&g_sel, sv);
            __threadfence();
            unsigned old = atomicAdd(&g_done, 1u);
            if (old == (unsigned)(NBLOCKS - 1)) {
                __threadfence();
                double n_noobj = (double)(TOTAL_CELLS + (long long)g_cnt);
                res[0] = g_sel + (float)(g_conf2 / n_noobj);
                g_conf2 = 0.0; g_cnt = 0ull; g_sel = 0.0f; g_done = 0u;
            }
        }
    }
}

extern "C" void kernel_launch(void* const* d_in, const int* in_sizes, int n_in,
                              void* d_out, int out_size) {
    const float* out = (const float*)d_in[0];   // (128, 10, 128, 128)
    const float* tgt = (const float*)d_in[1];   // (128, 4)
    const float* anc = (const float*)d_in[2];   // (2, 2)
    float* res = (float*)d_out;

    k_fused<<<NBLOCKS, 256>>>(out, tgt, anc, res);
}

// round 12
// speedup vs baseline: 1.1352x; 1.0312x over previous
#include <cuda_runtime.h>
#include <math.h>
#include <float.h>

constexpr int NB = 128, NA = 2, NH = 128, NW = 128;
constexpr int PLANE = NH * NW;
constexpr int ROFF  = 64 * NW;             // second-row offset (row j+64)
constexpr float THRESH = 0.6f;
constexpr float OBJ_SCALE = 5.0f;
constexpr float LN_MARGIN = 0.55961579f;   // ln(1.75) > ln(5/3)+fastlog-err margin
constexpr float POS_MARGIN = 1.30f;        // > 1.2889 exact positional bound
constexpr int NBLOCKS = 1024;              // 262144 threads * 16 cells
constexpr long long TOTAL_CELLS = (long long)NB * NA * NH * NW;  // 4194304

// Accumulators (zero at module load; reset by last block each run)
__device__ double g_conf2 = 0.0;
__device__ unsigned long long g_cnt = 0ull;   // corrections only (negative)
__device__ float  g_sel = 0.0f;
__device__ unsigned g_done = 0u;

__device__ __forceinline__ float sig_fast(float x) {
    return __fdividef(1.0f, 1.0f + __expf(-x));
}

struct RowData { float w[8], h[8], c[8]; };

// Hot pass over one row: unconditional conf^2 + min-distance screen.
__device__ __forceinline__ void hot_row(const RowData& d, float cc,
                                        float& conf2f, float& dmin) {
    #pragma unroll
    for (int k = 0; k < 8; k++) {
        float s = d.w[k] + d.h[k];
        dmin = fminf(dmin, fabsf(s - cc));
        float rr = sig_fast(d.c[k]);
        conf2f += rr * rr;
    }
}

// Rare pass: corrections for iou>THRESH cells + excluded cell + sel loss.
__device__ __forceinline__ void slow_row(
    const RowData& d, const float* prow, int i8, float fj, int kx, float cc,
    float aw, float ah, float gx, float gy, float gw, float gh, float ga,
    float bw, float bh, float tscale,
    float& conf2f, int& cnt, float& selv)
{
    float4 x0 = *(const float4*)(prow);
    float4 x1 = *(const float4*)(prow + 4);
    float4 y0 = *(const float4*)(prow + (size_t)PLANE);
    float4 y1 = *(const float4*)(prow + (size_t)PLANE + 4);
    float px8[8] = {x0.x,x0.y,x0.z,x0.w,x1.x,x1.y,x1.z,x1.w};
    float py8[8] = {y0.x,y0.y,y0.z,y0.w,y1.x,y1.y,y1.z,y1.w};

    float gxm = gx - gw * 0.5f, gxM = gx + gw * 0.5f;
    float gym = gy - gh * 0.5f, gyM = gy + gh * 0.5f;

    #pragma unroll
    for (int k = 0; k < 8; k++) {          // compile-time indices only
        bool is_excl = (k == kx);
        bool pass = fabsf(d.w[k] + d.h[k] - cc) < LN_MARGIN;
        if (pass | is_excl) {
            float px = sig_fast(px8[k]) + (float)(i8 + k);
            float py = sig_fast(py8[k]) + fj;
            float pw = __expf(d.w[k]) * aw;
            float ph = __expf(d.h[k]) * ah;
            float mx = fminf(px - pw * 0.5f, gxm);
            float Mx = fmaxf(px + pw * 0.5f, gxM);
            float my = fminf(py - ph * 0.5f, gym);
            float My = fmaxf(py + ph * 0.5f, gyM);
            float cw = pw + gw - (Mx - mx);
            float ch = ph + gh - (My - my);
            float carea = cw * ch;
            float uarea = pw * ph + ga - carea;
            bool noobj = (cw <= 0.0f) || (ch <= 0.0f) || (carea <= THRESH * uarea);
            if ((pass && !noobj) || is_excl) {
                float rr = sig_fast(d.c[k]);   // identical recompute: exact cancel
                conf2f -= rr * rr;
                cnt--;
            }
            if (is_excl) {
                float xs = sig_fast(px8[k]);
                float ys = sig_fast(py8[k]);
                float cs = sig_fast(d.c[k]);
                float txv = gx - floorf(gx), tyv = gy - floorf(gy);
                float twv = __logf(__fdividef(gw, bw) + 1e-16f);
                float thv = __logf(__fdividef(gh, bh) + 1e-16f);
                float dx = (xs - txv) * tscale, dy = (ys - tyv) * tscale;
                float dw = (d.w[k] - twv) * tscale, dh = (d.h[k] - thv) * tscale;
                selv += (dx*dx + dy*dy + dw*dw + dh*dh
                      + OBJ_SCALE * (cs - 1.0f) * (cs - 1.0f)) * (1.0f / (float)NB);
            }
        }
    }
}

__global__ void k_fused(const float* __restrict__ out,
                        const float* __restrict__ tgt,
                        const float* __restrict__ anc,
                        float* __restrict__ res) {
    int tid = blockIdx.x * 256 + threadIdx.x;
    int i8 = (tid & 15) * 8;          // 8 contiguous columns
    int r  = tid >> 4;
    int j  = r & 63; r >>= 6;         // rows j and j+64
    int a  = r & 1;                   // anchor (block-uniform)
    int b  = r >> 1;                  // batch  (block-uniform)

    // ---- 12 front-batched float4 loads: w,h,c for rows j and j+64 ----
    const float* pbase = out + ((size_t)(b * 10 + a * 5) * NH + j) * NW + i8;
    float4 wA0 = *(const float4*)(pbase + 2 * (size_t)PLANE);
    float4 wA1 = *(const float4*)(pbase + 2 * (size_t)PLANE + 4);
    float4 wB0 = *(const float4*)(pbase + 2 * (size_t)PLANE + ROFF);
    float4 wB1 = *(const float4*)(pbase + 2 * (size_t)PLANE + ROFF + 4);
    float4 hA0 = *(const float4*)(pbase + 3 * (size_t)PLANE);
    float4 hA1 = *(const float4*)(pbase + 3 * (size_t)PLANE + 4);
    float4 hB0 = *(const float4*)(pbase + 3 * (size_t)PLANE + ROFF);
    float4 hB1 = *(const float4*)(pbase + 3 * (size_t)PLANE + ROFF + 4);
    float4 cA0 = *(const float4*)(pbase + 4 * (size_t)PLANE);
    float4 cA1 = *(const float4*)(pbase + 4 * (size_t)PLANE + 4);
    float4 cB0 = *(const float4*)(pbase + 4 * (size_t)PLANE + ROFF);
    float4 cB1 = *(const float4*)(pbase + 4 * (size_t)PLANE + ROFF + 4);

    // ---- lean per-thread constants ----
    float4 t = __ldg((const float4*)(tgt + b * 4));     // warp-broadcast
    float gx = t.x * (float)NW, gy = t.y * (float)NH;
    float gw = t.z * (float)NW, gh = t.w * (float)NH;
    float a0w = __ldg(anc + 0), a0h = __ldg(anc + 1);
    float a1w = __ldg(anc + 2), a1h = __ldg(anc + 3);
    float aw = a ? a1w : a0w;
    float ah = a ? a1h : a0h;
    float ga = gw * gh;
    float cc = __logf(__fdividef(ga, aw * ah));

    // position screen at row granularity: row can't reach iou>0.6 -> cc=inf
    float fjA = (float)j, fjB = (float)(j + 64);
    bool colok = ((float)(i8 + 7) > gx - POS_MARGIN * gw - 1.0f) &&
                 ((float)i8      < gx + POS_MARGIN * gw);
    float gylo = gy - POS_MARGIN * gh - 1.0f, gyhi = gy + POS_MARGIN * gh;
    float ccA = (colok && fjA > gylo && fjA < gyhi) ? cc : FLT_MAX;
    float ccB = (colok && fjB > gylo && fjB < gyhi) ? cc : FLT_MAX;

    // lazy exclusion bookkeeping (taken by ~2 threads per batch)
    int gxi = (int)gx, gyi = (int)gy;
    int kxA = -1, kxB = -1;
    int colk = gxi - i8;
    if ((unsigned)colk < 8u && (gyi == j || gyi == j + 64)) {
        float i0v = fminf(gw, a0w) * fminf(gh, a0h);
        float u0v = ga + 1e-16f + a0w * a0h - i0v;
        float i1v = fminf(gw, a1w) * fminf(gh, a1h);
        float u1v = ga + 1e-16f + a1w * a1h - i1v;
        int best = (i1v * u0v > i0v * u1v) ? 1 : 0;
        if (best == a) {
            if (gyi == j) kxA = colk; else kxB = colk;
        }
    }

    RowData dA, dB;
    dA.w[0]=wA0.x; dA.w[1]=wA0.y; dA.w[2]=wA0.z; dA.w[3]=wA0.w;
    dA.w[4]=wA1.x; dA.w[5]=wA1.y; dA.w[6]=wA1.z; dA.w[7]=wA1.w;
    dA.h[0]=hA0.x; dA.h[1]=hA0.y; dA.h[2]=hA0.z; dA.h[3]=hA0.w;
    dA.h[4]=hA1.x; dA.h[5]=hA1.y; dA.h[6]=hA1.z; dA.h[7]=hA1.w;
    dA.c[0]=cA0.x; dA.c[1]=cA0.y; dA.c[2]=cA0.z; dA.c[3]=cA0.w;
    dA.c[4]=cA1.x; dA.c[5]=cA1.y; dA.c[6]=cA1.z; dA.c[7]=cA1.w;
    dB.w[0]=wB0.x; dB.w[1]=wB0.y; dB.w[2]=wB0.z; dB.w[3]=wB0.w;
    dB.w[4]=wB1.x; dB.w[5]=wB1.y; dB.w[6]=wB1.z; dB.w[7]=wB1.w;
    dB.h[0]=hB0.x; dB.h[1]=hB0.y; dB.h[2]=hB0.z; dB.h[3]=hB0.w;
    dB.h[4]=hB1.x; dB.h[5]=hB1.y; dB.h[6]=hB1.z; dB.h[7]=hB1.w;
    dB.c[0]=cB0.x; dB.c[1]=cB0.y; dB.c[2]=cB0.z; dB.c[3]=cB0.w;
    dB.c[4]=cB1.x; dB.c[5]=cB1.y; dB.c[6]=cB1.z; dB.c[7]=cB1.w;

    // ---- hot loops ----
    float conf2f = 0.0f;
    float dminA = FLT_MAX, dminB = FLT_MAX;
    hot_row(dA, ccA, conf2f, dminA);
    hot_row(dB, ccB, conf2f, dminB);

    // ---- rare slow paths ----
    float selv = 0.0f;
    int cnt = 0;
    if ((dminA < LN_MARGIN) | (kxA >= 0) | (dminB < LN_MARGIN) | (kxB >= 0)) {
        float bw = a1w, bh = a1h, tscale = 2.0f - t.z * t.w;
        {   // best anchor dims (recompute; rare)
            float i0v = fminf(gw, a0w) * fminf(gh, a0h);
            float u0v = ga + 1e-16f + a0w * a0h - i0v;
            float i1v = fminf(gw, a1w) * fminf(gh, a1h);
            float u1v = ga + 1e-16f + a1w * a1h - i1v;
            if (!(i1v * u0v > i0v * u1v)) { bw = a0w; bh = a0h; }
        }
        if ((dminA < LN_MARGIN) | (kxA >= 0))
            slow_row(dA, pbase, i8, fjA, kxA, ccA, aw, ah,
                     gx, gy, gw, gh, ga, bw, bh, tscale, conf2f, cnt, selv);
        if ((dminB < LN_MARGIN) | (kxB >= 0))
            slow_row(dB, pbase + ROFF, i8, fjB, kxB, ccB, aw, ah,
                     gx, gy, gw, gh, ga, bw, bh, tscale, conf2f, cnt, selv);
    }

    // ---- block reduce (conf2, cnt, selv) ----
    #pragma unroll
    for (int o = 16; o > 0; o >>= 1) {
        conf2f += __shfl_down_sync(0xffffffffu, conf2f, o);
        cnt    += __shfl_down_sync(0xffffffffu, cnt, o);
        selv   += __shfl_down_sync(0xffffffffu, selv, o);
    }
    __shared__ double sh_c2[8];
    __shared__ int    sh_ct[8];
    __shared__ float  sh_sv[8];
    int lane = threadIdx.x & 31, wrp = threadIdx.x >> 5;
    if (lane == 0) { sh_c2[wrp] = (double)conf2f; sh_ct[wrp] = cnt; sh_sv[wrp] = selv; }
    __syncthreads();
    if (wrp == 0) {
        double c2 = (lane < 8) ? sh_c2[lane] : 0.0;
        int    ct = (lane < 8) ? sh_ct[lane] : 0;
        float  sv = (lane < 8) ? sh_sv[lane] : 0.0f;
        #pragma unroll
        for (int o = 4; o > 0; o >>= 1) {
            c2 += __shfl_down_sync(0xffffffffu, c2, o);
            ct += __shfl_down_sync(0xffffffffu, ct, o);
            sv += __shfl_down_sync(0xffffffffu, sv, o);
        }
        if (lane == 0) {
            atomicAdd(&g_conf2, c2);
            if (ct != 0) atomicAdd(&g_cnt, (unsigned long long)(long long)ct);
            if (sv != 0.0f) atomicAdd(&g_sel, sv);
            __threadfence();
            unsigned old = atomicAdd(&g_done, 1u);
            if (old == (unsigned)(NBLOCKS - 1)) {
                __threadfence();
                double n_noobj = (double)(TOTAL_CELLS + (long long)g_cnt);
                res[0] = g_sel + (float)(g_conf2 / n_noobj);
                g_conf2 = 0.0; g_cnt = 0ull; g_sel = 0.0f; g_done = 0u;
            }
        }
    }
}

extern "C" void kernel_launch(void* const* d_in, const int* in_sizes, int n_in,
                              void* d_out, int out_size) {
    const float* out = (const float*)d_in[0];   // (128, 10, 128, 128)
    const float* tgt = (const float*)d_in[1];   // (128, 4)
    const float* anc = (const float*)d_in[2];   // (2, 2)
    float* res = (float*)d_out;

    k_fused<<<NBLOCKS, 256>>>(out, tgt, anc, res);
}

// round 13
// speedup vs baseline: 1.2243x; 1.0785x over previous
#include <cuda_runtime.h>
#include <math.h>
#include <float.h>
#include <stdint.h>

constexpr int NB = 128, NA = 2, NH = 128, NW = 128;
constexpr int PLANE = NH * NW;
constexpr float THRESH = 0.6f;
constexpr float OBJ_SCALE = 5.0f;
constexpr float LN_MARGIN = 0.55961579f;   // ln(1.75) > ln(5/3)+fastlog-err margin
constexpr float POS_MARGIN = 1.30f;        // > 1.2889 exact positional bound
constexpr int ROWS_PER_BLOCK = 32;
constexpr int ROWS_PER_STAGE = 8;
constexpr int NSTAGES = ROWS_PER_BLOCK / ROWS_PER_STAGE;    // 4
constexpr int NBLOCKS = NB * NA * (NH / ROWS_PER_BLOCK);    // 1024
constexpr long long TOTAL_CELLS = (long long)NB * NA * NH * NW;
constexpr int STAGE_FLOATS = ROWS_PER_STAGE * NW;           // 1024 per plane
constexpr unsigned STAGE_BYTES_PLANE = STAGE_FLOATS * 4;    // 4096
constexpr unsigned STAGE_BYTES = STAGE_BYTES_PLANE * 3;     // 12288

// Accumulators (zero at module load; reset by last block each run)
__device__ double g_conf2 = 0.0;
__device__ unsigned long long g_cnt = 0ull;   // corrections only (negative)
__device__ float  g_sel = 0.0f;
__device__ unsigned g_done = 0u;

__device__ __forceinline__ float sig_fast(float x) {
    return __fdividef(1.0f, 1.0f + __expf(-x));
}
__device__ __forceinline__ uint32_t s2u(const void* p) {
    uint32_t r;
    asm("{ .reg .u64 t; cvta.to.shared.u64 t, %1; cvt.u32.u64 %0, t; }"
        : "=r"(r) : "l"(p));
    return r;
}
__device__ __forceinline__ void mbar_init(uint32_t mb, uint32_t cnt) {
    asm volatile("mbarrier.init.shared.b64 [%0], %1;" :: "r"(mb), "r"(cnt) : "memory");
}
__device__ __forceinline__ void mbar_expect(uint32_t mb, uint32_t bytes) {
    asm volatile("mbarrier.arrive.expect_tx.shared.b64 _, [%0], %1;"
                 :: "r"(mb), "r"(bytes) : "memory");
}
__device__ __forceinline__ void mbar_wait(uint32_t mb, uint32_t parity) {
    asm volatile(
        "{\n\t.reg .pred P;\n\t"
        "WL_%=:\n\t"
        "mbarrier.try_wait.parity.acquire.cta.shared::cta.b64 P, [%0], %1, 0x989680;\n\t"
        "@P bra.uni WD_%=;\n\t"
        "bra.uni WL_%=;\n\t"
        "WD_%=:\n\t}"
        :: "r"(mb), "r"(parity) : "memory");
}
__device__ __forceinline__ void bulk_g2s(uint32_t sdst, const float* gsrc,
                                         uint32_t bytes, uint32_t mb) {
    asm volatile(
        "cp.async.bulk.shared::cta.global.mbarrier::complete_tx::bytes "
        "[%0], [%1], %2, [%3];"
        :: "r"(sdst), "l"(gsrc), "r"(bytes), "r"(mb) : "memory");
}

__global__ void __launch_bounds__(256) k_fused(const float* __restrict__ out,
                                               const float* __restrict__ tgt,
                                               const float* __restrict__ anc,
                                               float* __restrict__ res) {
    __shared__ __align__(128) float sbuf[2][3][STAGE_FLOATS];   // 24 KB
    __shared__ unsigned long long mbar[2];
    __shared__ double sh_c2[8];
    __shared__ int    sh_ct[8];
    __shared__ float  sh_sv[8];

    int tid = threadIdx.x;
    int blk = blockIdx.x;
    int seg  = blk & 3;           // which 32-row segment
    int slab = blk >> 2;          // b*2 + a
    int a = slab & 1;
    int b = slab >> 1;
    int j0 = seg * ROWS_PER_BLOCK;

    const float* slabp = out + (size_t)(b * 10 + a * 5) * PLANE;
    uint32_t mb[2] = { s2u(&mbar[0]), s2u(&mbar[1]) };

    if (tid == 0) { mbar_init(mb[0], 1); mbar_init(mb[1], 1); }
    __syncthreads();

    // issue stages 0 and 1 (w,h,c planes)
    if (tid == 0) {
        #pragma unroll
        for (int s = 0; s < 2; s++) {
            mbar_expect(mb[s], STAGE_BYTES);
            #pragma unroll
            for (int p = 0; p < 3; p++)
                bulk_g2s(s2u(&sbuf[s][p][0]),
                         slabp + (size_t)(p + 2) * PLANE + (j0 + s * ROWS_PER_STAGE) * NW,
                         STAGE_BYTES_PLANE, mb[s]);
        }
    }

    // ---- per-thread constants ----
    float4 t = __ldg((const float4*)(tgt + b * 4));
    float gx = t.x * (float)NW, gy = t.y * (float)NH;
    float gw = t.z * (float)NW, gh = t.w * (float)NH;
    float a0w = __ldg(anc + 0), a0h = __ldg(anc + 1);
    float a1w = __ldg(anc + 2), a1h = __ldg(anc + 3);
    float aw = a ? a1w : a0w;
    float ah = a ? a1h : a0h;
    float ga = gw * gh;
    float cc = __logf(__fdividef(ga, aw * ah));

    int r  = tid >> 5;            // row within stage (0..7)
    int c4 = (tid & 31) * 4;      // 4 contiguous columns
    bool colok = ((float)(c4 + 3) > gx - POS_MARGIN * gw - 1.0f) &&
                 ((float)c4       < gx + POS_MARGIN * gw);
    float gylo = gy - POS_MARGIN * gh - 1.0f, gyhi = gy + POS_MARGIN * gh;
    int gxi = (int)gx, gyi = (int)gy;
    int colk = gxi - c4;          // [0,4) iff this thread's col window owns gt col
    bool colown = (unsigned)colk < 4u;

    float conf2f = 0.0f;
    float selv = 0.0f;
    int cnt = 0;

    for (int s = 0; s < NSTAGES; s++) {
        int buf = s & 1;
        mbar_wait(mb[buf], (s >> 1) & 1);

        int j = j0 + s * ROWS_PER_STAGE + r;
        float fj = (float)j;
        float4 w4 = *(const float4*)&sbuf[buf][0][r * NW + c4];
        float4 h4 = *(const float4*)&sbuf[buf][1][r * NW + c4];
        float4 cf4 = *(const float4*)&sbuf[buf][2][r * NW + c4];
        float pw4[4] = {w4.x, w4.y, w4.z, w4.w};
        float ph4[4] = {h4.x, h4.y, h4.z, h4.w};
        float pc4[4] = {cf4.x, cf4.y, cf4.z, cf4.w};

        float ccS = (colok && fj > gylo && fj < gyhi) ? cc : FLT_MAX;

        // hot: unconditional conf^2 + min-distance screen
        float dmin = FLT_MAX;
        #pragma unroll
        for (int k = 0; k < 4; k++) {
            dmin = fminf(dmin, fabsf(pw4[k] + ph4[k] - ccS));
            float rr = sig_fast(pc4[k]);
            conf2f += rr * rr;
        }

        // lazy exclusion: does this thread own the gt cell this stage?
        int kx = -1;
        if (colown && gyi == j) {
            float i0v = fminf(gw, a0w) * fminf(gh, a0h);
            float u0v = ga + 1e-16f + a0w * a0h - i0v;
            float i1v = fminf(gw, a1w) * fminf(gh, a1h);
            float u1v = ga + 1e-16f + a1w * a1h - i1v;
            int best = (i1v * u0v > i0v * u1v) ? 1 : 0;
            if (best == a) kx = colk;
        }

        if ((dmin < LN_MARGIN) | (kx >= 0)) {
            // rare slow path: x/y direct from GMEM
            const float* prow = slabp + (size_t)j * NW + c4;
            float4 x4 = __ldg((const float4*)(prow));
            float4 y4 = __ldg((const float4*)(prow + (size_t)PLANE));
            float px4[4] = {x4.x, x4.y, x4.z, x4.w};
            float py4[4] = {y4.x, y4.y, y4.z, y4.w};
            float gxm = gx - gw * 0.5f, gxM = gx + gw * 0.5f;
            float gym = gy - gh * 0.5f, gyM = gy + gh * 0.5f;

            #pragma unroll
            for (int k = 0; k < 4; k++) {       // compile-time indices
                bool is_excl = (k == kx);
                bool pass = fabsf(pw4[k] + ph4[k] - ccS) < LN_MARGIN;
                if (pass | is_excl) {
                    float px = sig_fast(px4[k]) + (float)(c4 + k);
                    float py = sig_fast(py4[k]) + fj;
                    float pw = __expf(pw4[k]) * aw;
                    float ph = __expf(ph4[k]) * ah;
                    float mx = fminf(px - pw * 0.5f, gxm);
                    float Mx = fmaxf(px + pw * 0.5f, gxM);
                    float my = fminf(py - ph * 0.5f, gym);
                    float My = fmaxf(py + ph * 0.5f, gyM);
                    float cw = pw + gw - (Mx - mx);
                    float ch = ph + gh - (My - my);
                    float carea = cw * ch;
                    float uarea = pw * ph + ga - carea;
                    bool noobj = (cw <= 0.0f) || (ch <= 0.0f) ||
                                 (carea <= THRESH * uarea);
                    if ((pass && !noobj) || is_excl) {
                        float rr = sig_fast(pc4[k]);   // exact cancel
                        conf2f -= rr * rr;
                        cnt--;
                    }
                    if (is_excl) {
                        float bw = aw, bh = ah;        // best==a here
                        float tscale = 2.0f - t.z * t.w;
                        float xs = sig_fast(px4[k]);
                        float ys = sig_fast(py4[k]);
                        float cs = sig_fast(pc4[k]);
                        float txv = gx - floorf(gx), tyv = gy - floorf(gy);
                        float twv = __logf(__fdividef(gw, bw) + 1e-16f);
                        float thv = __logf(__fdividef(gh, bh) + 1e-16f);
                        float dx = (xs - txv) * tscale, dy = (ys - tyv) * tscale;
                        float dw = (pw4[k] - twv) * tscale;
                        float dh = (ph4[k] - thv) * tscale;
                        selv += (dx*dx + dy*dy + dw*dw + dh*dh
                              + OBJ_SCALE * (cs - 1.0f) * (cs - 1.0f))
                              * (1.0f / (float)NB);
                    }
                }
            }
        }

        __syncthreads();            // all threads done reading sbuf[buf]
        if (tid == 0 && s + 2 < NSTAGES) {
            int ns = s + 2;
            mbar_expect(mb[buf], STAGE_BYTES);
            #pragma unroll
            for (int p = 0; p < 3; p++)
                bulk_g2s(s2u(&sbuf[buf][p][0]),
                         slabp + (size_t)(p + 2) * PLANE + (j0 + ns * ROWS_PER_STAGE) * NW,
                         STAGE_BYTES_PLANE, mb[buf]);
        }
    }

    // ---- block reduce (conf2, cnt, selv) ----
    #pragma unroll
    for (int o = 16; o > 0; o >>= 1) {
        conf2f += __shfl_down_sync(0xffffffffu, conf2f, o);
        cnt    += __shfl_down_sync(0xffffffffu, cnt, o);
        selv   += __shfl_down_sync(0xffffffffu, selv, o);
    }
    int lane = tid & 31, wrp = tid >> 5;
    if (lane == 0) { sh_c2[wrp] = (double)conf2f; sh_ct[wrp] = cnt; sh_sv[wrp] = selv; }
    __syncthreads();
    if (wrp == 0) {
        double c2 = (lane < 8) ? sh_c2[lane] : 0.0;
        int    ct = (lane < 8) ? sh_ct[lane] : 0;
        float  sv = (lane < 8) ? sh_sv[lane] : 0.0f;
        #pragma unroll
        for (int o = 4; o > 0; o >>= 1) {
            c2 += __shfl_down_sync(0xffffffffu, c2, o);
            ct += __shfl_down_sync(0xffffffffu, ct, o);
            sv += __shfl_down_sync(0xffffffffu, sv, o);
        }
        if (lane == 0) {
            atomicAdd(&g_conf2, c2);
            if (ct != 0) atomicAdd(&g_cnt, (unsigned long long)(long long)ct);
            if (sv != 0.0f) atomicAdd(&g_sel, sv);
            __threadfence();
            unsigned old = atomicAdd(&g_done, 1u);
            if (old == (unsigned)(NBLOCKS - 1)) {
                __threadfence();
                double n_noobj = (double)(TOTAL_CELLS + (long long)g_cnt);
                res[0] = g_sel + (float)(g_conf2 / n_noobj);
                g_conf2 = 0.0; g_cnt = 0ull; g_sel = 0.0f; g_done = 0u;
            }
        }
    }
}

extern "C" void kernel_launch(void* const* d_in, const int* in_sizes, int n_in,
                              void* d_out, int out_size) {
    const float* out = (const float*)d_in[0];   // (128, 10, 128, 128)
    const float* tgt = (const float*)d_in[1];   // (128, 4)
    const float* anc = (const float*)d_in[2];   // (2, 2)
    float* res = (float*)d_out;

    k_fused<<<NBLOCKS, 256>>>(out, tgt, anc, res);
}